// round 17
// baseline (speedup 1.0000x reference)
#include <cuda_runtime.h>
#include <cstdint>

// ROI Align, NCHW.  input (4,256,200,200) f32, rois (1024,5), out (1024,256,7,7).
// R16 resubmit (broker infra failure, as R3/R13). Warp-autonomous pipelines,
// depth 4: each warp owns 8 channels = 8 groups of 1 channel, 4 smem buffers,
// wait_group<3> keeps 3-4 groups in flight per warp (vs ~1.5 at depth 2).
// No CTA barriers. launch_bounds(128,12) for 12 CTAs/SM.

#define OHW 49
static constexpr int C_   = 256;
static constexpr int H_   = 200;
static constexpr int W_   = 200;
static constexpr int HW_  = H_ * W_;
static constexpr int P_   = 20;             // smem row pitch (floats) = 5 quads
static constexpr int CSTR = 16 * P_ + 4;    // 324 floats per channel plane
static constexpr int NT   = 128;
static constexpr int NG   = 8;              // groups (channels) per warp

__device__ __forceinline__ void cp_async16(uint32_t s_dst, const void* g_src) {
    asm volatile("cp.async.cg.shared.global [%0], [%1], 16;" :: "r"(s_dst), "l"(g_src));
}
__device__ __forceinline__ void cp_commit() {
    asm volatile("cp.async.commit_group;" ::: "memory");
}
template <int N> __device__ __forceinline__ void cp_wait() {
    asm volatile("cp.async.wait_group %0;" :: "n"(N) : "memory");
}

__global__ __launch_bounds__(NT, 12) void roi_align_kernel(
    const float* __restrict__ inp,
    const float* __restrict__ rois,
    float* __restrict__ out)
{
    // tile[buf 0..3][warp][plane] : 4*4*324*4 = 20736 B
    __shared__ __align__(16) float tile[4][4][CSTR];

    const int m    = blockIdx.x;
    const int c0   = blockIdx.y * 32;
    const int tid  = threadIdx.x;
    const int wid  = tid >> 5;
    const int lane = tid & 31;

    // ---- per-roi scalars (proven math; uniform across warp) ----
    const float* r = rois + (size_t)m * 5;
    const int   b  = (int)r[0];
    const float x1 = r[1] * 0.25f, y1 = r[2] * 0.25f;
    const float bw = fmaxf(r[3] * 0.25f - x1, 1.0f) * (1.0f / 7.0f);
    const float bh = fmaxf(r[4] * 0.25f - y1, 1.0f) * (1.0f / 7.0f);

    const float px0f = ((x1 + 0.5f * bw) * 199.0f) / 200.0f;
    const float px6f = ((x1 + 6.5f * bw) * 199.0f) / 200.0f;
    const float py0f = ((y1 + 0.5f * bh) * 199.0f) / 200.0f;
    const float py6f = ((y1 + 6.5f * bh) * 199.0f) / 200.0f;
    int xlo = max(0, min((int)floorf(px0f), W_ - 1));
    int ylo = max(0, min((int)floorf(py0f), H_ - 1));
    int xhi = max(xlo, min((int)floorf(px6f) + 1, W_ - 1));
    int yhi = max(ylo, min((int)floorf(py6f) + 1, H_ - 1));
    const int ww = min(xhi - xlo + 1, 16);
    const int wh = min(yhi - ylo + 1, 16);
    const int ax = min(xlo & ~3, W_ - P_);
    const int nq = min(5, (xlo - ax + ww + 3) >> 2);

    // ---- staging lane map: one channel per stage; lane -> (row0, q) ----
    const int row0 = lane / 5;               // 0..6 (lanes 30,31 idle)
    const int q    = lane - row0 * 5;        // 0..4
    const bool lact = (lane < 30) && (q < nq);

    bool     pk[3];
    uint32_t sok[3];
    int      gok[3];
    #pragma unroll
    for (int k = 0; k < 3; k++) {
        const int y = row0 + 6 * k;
        pk[k]  = lact && (y < wh);
        sok[k] = (uint32_t)(y * P_ + q * 4) * 4u;
        gok[k] = y * W_ + q * 4;
    }
    const float* cb = inp + ((size_t)(b * C_ + c0 + NG * wid)) * HW_
                          + (size_t)ylo * W_ + ax;
    const uint32_t spw = (uint32_t)__cvta_generic_to_shared(&tile[0][wid][0]);
    constexpr uint32_t BSTRIDE = 4u * CSTR * 4u;   // bytes between buffers

    auto stage = [&](int g) {
        const float* gp = cb + (size_t)g * HW_;
        const uint32_t sp = spw + (uint32_t)(g & 3) * BSTRIDE;
        #pragma unroll
        for (int k = 0; k < 3; k++)
            if (pk[k]) cp_async16(sp + sok[k], gp + gok[k]);
        cp_commit();
    };

    // ---- register-resident bin params: binA = lane, binB = lane+32 ----
    const bool vB = lane < 17;
    auto binparams = [&](int bin, float& w00, float& w01, float& w10, float& w11,
                         int& xryo) {
        const int ph = bin / 7;
        const int pw = bin - ph * 7;
        const float px = ((x1 + ((float)pw + 0.5f) * bw) * 199.0f) / 200.0f;
        const float py = ((y1 + ((float)ph + 0.5f) * bh) * 199.0f) / 200.0f;
        const int x0 = (int)floorf(px);
        const int y0 = (int)floorf(py);
        const float lx = px - (float)x0;
        const float ly = py - (float)y0;
        const float hx = 1.0f - lx, hy = 1.0f - ly;
        w00 = hy * hx; w01 = hy * lx; w10 = ly * hx; w11 = ly * lx;
        xryo = min(max(y0 - ylo, 0), 14) * P_ + min(max(x0 - ax, 0), P_ - 2);
    };

    float wA00, wA01, wA10, wA11, wB00, wB01, wB10, wB11;
    int xryoA, xryoB;
    binparams(lane, wA00, wA01, wA10, wA11, xryoA);
    binparams(lane + 32, wB00, wB01, wB10, wB11, xryoB);

    float* const outw = out + ((size_t)m * C_ + c0 + NG * wid) * OHW + lane;

    auto compute = [&](int g) {
        const float* tb = &tile[g & 3][wid][0];
        const float* tA = tb + xryoA;
        const float vA = wA00 * tA[0] + wA01 * tA[1]
                       + wA10 * tA[P_] + wA11 * tA[P_ + 1];
        __stcs(outw + g * OHW, vA);
        if (vB) {
            const float* tB = tb + xryoB;
            const float uB = wB00 * tB[0] + wB01 * tB[1]
                           + wB10 * tB[P_] + wB11 * tB[P_ + 1];
            __stcs(outw + g * OHW + 32, uB);
        }
    };

    // ---- per-warp pipeline, depth 4, no CTA barriers ----
    stage(0); stage(1); stage(2); stage(3);
    #pragma unroll
    for (int g = 0; g < NG; g++) {
        const int rem = NG - 1 - g;          // groups still outstanding after g
        if (rem >= 3)      cp_wait<3>();
        else if (rem == 2) cp_wait<2>();
        else if (rem == 1) cp_wait<1>();
        else               cp_wait<0>();
        __syncwarp();
        compute(g);
        __syncwarp();
        if (g + 4 < NG) stage(g + 4);
    }
}

extern "C" void kernel_launch(void* const* d_in, const int* in_sizes, int n_in,
                              void* d_out, int out_size)
{
    const float* inp  = (const float*)d_in[0];
    const float* rois = (const float*)d_in[1];
    float*       out  = (float*)d_out;
    const int M = in_sizes[1] / 5;           // 1024
    dim3 grid(M, C_ / 32);                   // (1024, 8)
    roi_align_kernel<<<grid, NT>>>(inp, rois, out);
}